// round 12
// baseline (speedup 1.0000x reference)
#include <cuda_runtime.h>
#include <math.h>

#define OBJ   224
#define NPIX  (OBJ*OBJ)
#define BB    8
#define NN_   2048
#define KNN   8
#define CH    64
#define CSTR  65
#define CONV_SMEM_FLOATS (324*CSTR + 4096)
#define CONV_SMEM_BYTES  (CONV_SMEM_FLOATS*4)

__device__ float d_params[BB][6];
__device__ float d_f0[BB*NN_*8];
__device__ float d_sq[BB*NN_];
__device__ int   d_knnidx[BB*NN_*KNN];
__device__ float d_g[BB*NN_*KNN*CH];
__device__ float d_stats[BB][4][2];
__device__ float d_f[BB*NN_*CH];
__device__ float d_res[BB*NPIX*CH];
__device__ float d_h1[BB*NPIX*CH];
__device__ float d_h2[BB*NPIX*CH];
__device__ float d_wt[2][9][64][64];
__constant__ float c_off9x[9] = {-1.f,-1.f,-1.f, 0.f,0.f,0.f, 1.f,1.f,1.f};
__constant__ float c_off9y[9] = {-1.f, 0.f, 1.f,-1.f,0.f,1.f,-1.f,0.f,1.f};

__global__ void k_zero() {
    size_t i = (size_t)blockIdx.x*blockDim.x + threadIdx.x;
    const size_t n4 = (size_t)BB*NPIX*CH/4;
    if (i < n4) ((float4*)d_res)[i] = make_float4(0.f,0.f,0.f,0.f);
}

__global__ void k_params(const float* __restrict__ pc) {
    int b = blockIdx.x, t = threadIdx.x;
    float mnx=1e30f, mxx=-1e30f, mny=1e30f, mxy=-1e30f;
    for (int n = t; n < NN_; n += 256) {
        float x = pc[(b*NN_+n)*3+0];
        float y = pc[(b*NN_+n)*3+1];
        mnx=fminf(mnx,x); mxx=fmaxf(mxx,x);
        mny=fminf(mny,y); mxy=fmaxf(mxy,y);
    }
    __shared__ float s0[256], s1[256], s2[256], s3[256];
    s0[t]=mnx; s1[t]=mxx; s2[t]=mny; s3[t]=mxy;
    __syncthreads();
    for (int st=128; st>0; st>>=1) {
        if (t < st) {
            s0[t]=fminf(s0[t],s0[t+st]); s1[t]=fmaxf(s1[t],s1[t+st]);
            s2[t]=fminf(s2[t],s2[t+st]); s3[t]=fmaxf(s3[t],s3[t+st]);
        }
        __syncthreads();
    }
    if (t == 0) {
        float rx = __fadd_rn(s1[0], -s0[0]);
        float ry = __fadd_rn(s3[0], -s2[0]);
        // PROBE: approximate division (div.approx.f32) — XLA:GPU fast fp32 divide
        float grid = __fdividef(fmaxf(rx, ry), (float)(OBJ-3));
        float imx = floorf(__fdividef(rx, grid));
        float imy = floorf(__fdividef(ry, grid));
        float cx = floorf((imx + 2.0f) * 0.5f);   // exact integers
        float cy = floorf((imy + 2.0f) * 0.5f);
        float offx = (float)(OBJ/2) - cx - 1.0f;
        float offy = (float)(OBJ/2) - cy - 1.0f;
        d_params[b][0]=s0[0]; d_params[b][1]=s2[0]; d_params[b][2]=grid;
        d_params[b][3]=offx + 1.0f;   // base offset includes the "+1"
        d_params[b][4]=offy + 1.0f;
    }
}

__global__ void k_f0(const float* __restrict__ pc, const float* __restrict__ w_in,
                     const float* __restrict__ b_in) {
    int i = blockIdx.x*256 + threadIdx.x;
    if (i >= BB*NN_) return;
    float x = pc[i*3+0], y = pc[i*3+1], z = pc[i*3+2];
    // sq = ((rn(x*x) + rn(y*y)) + rn(z*z)) — matches jnp.sum(coor*coor)
    d_sq[i] = __fadd_rn(__fadd_rn(__fmul_rn(x,x), __fmul_rn(y,y)), __fmul_rn(z,z));
    #pragma unroll
    for (int o = 0; o < 8; o++) {
        float a = 0.f;
        a = fmaf(x, w_in[o*3+0], a);
        a = fmaf(y, w_in[o*3+1], a);
        a = fmaf(z, w_in[o*3+2], a);
        d_f0[i*8 + o] = a + b_in[o];
    }
}

// KNN: ascending-FMA dot (cuBLAS SGEMM K=3 inner-loop form)
__global__ void k_knn(const float* __restrict__ pc) {
    int b = blockIdx.y;
    int q = blockIdx.x*256 + threadIdx.x;
    const float* P = pc + (size_t)b*NN_*3;
    float qx = P[q*3+0], qy = P[q*3+1], qz = P[q*3+2];
    float qsq = d_sq[b*NN_ + q];
    __shared__ float4 sp[256];
    float bd[8]; int bi[8];
    #pragma unroll
    for (int k = 0; k < 8; k++) { bd[k] = 3.4e38f; bi[k] = 0; }
    for (int t0 = 0; t0 < NN_; t0 += 256) {
        int j = t0 + threadIdx.x;
        sp[threadIdx.x] = make_float4(P[j*3+0], P[j*3+1], P[j*3+2], d_sq[b*NN_ + j]);
        __syncthreads();
        for (int jj = 0; jj < 256; jj++) {
            float4 c = sp[jj];
            float dot = fmaf(qz, c.z, fmaf(qy, c.y, __fmul_rn(qx, c.x)));
            float tt  = __fadd_rn(qsq, c.w);
            float dd  = __fadd_rn(tt, -__fmul_rn(2.0f, dot));
            if (dd < bd[7]) {          // strict <: ties keep earlier (lower) index
                float cd = dd; int ci = t0 + jj;
                #pragma unroll
                for (int k = 0; k < 8; k++) {
                    if (cd < bd[k]) {
                        float td = bd[k]; int ti = bi[k];
                        bd[k] = cd; bi[k] = ci;
                        cd = td; ci = ti;
                    }
                }
            }
        }
        __syncthreads();
    }
    #pragma unroll
    for (int k = 0; k < 8; k++) d_knnidx[(b*NN_ + q)*KNN + k] = bi[k];
}

__global__ void k_graph(const float* __restrict__ wg) {
    int gid = blockIdx.x*256 + threadIdx.x;
    if (gid >= BB*NN_*KNN*CH) return;
    int o  = gid & 63;
    int k  = (gid >> 6) & 7;
    int nn = gid >> 9;
    int b  = nn >> 11;
    int nbr = d_knnidx[nn*KNN + k];
    const float* fq = d_f0 + nn*8;
    const float* fn = d_f0 + (b*NN_ + nbr)*8;
    const float* w  = wg + o*16;
    float acc = 0.f;
    #pragma unroll
    for (int c = 0; c < 8; c++)
        acc = fmaf(__fadd_rn(fn[c], -fq[c]), w[c], acc);
    #pragma unroll
    for (int c = 0; c < 8; c++)
        acc = fmaf(fq[c], w[8+c], acc);
    d_g[gid] = acc;
}

__global__ void k_mean() {
    int bg = blockIdx.x; int b = bg >> 2, grp = bg & 3;
    int t = threadIdx.x;
    const float* base = d_g + (size_t)b*NN_*KNN*CH + grp*16;
    float s = 0.f;
    const int M = NN_*KNN*16;
    for (int i = t; i < M; i += 512) {
        int c = i & 15; int nk = i >> 4;
        s += base[(size_t)nk*CH + c];
    }
    __shared__ float ss[512];
    ss[t] = s;
    __syncthreads();
    for (int st = 256; st > 0; st >>= 1) {
        if (t < st) ss[t] += ss[t+st];
        __syncthreads();
    }
    if (t == 0) d_stats[b][grp][0] = ss[0] / (float)M;
}

__global__ void k_var() {
    int bg = blockIdx.x; int b = bg >> 2, grp = bg & 3;
    int t = threadIdx.x;
    const float* base = d_g + (size_t)b*NN_*KNN*CH + grp*16;
    float mean = d_stats[b][grp][0];
    float s = 0.f;
    const int M = NN_*KNN*16;
    for (int i = t; i < M; i += 512) {
        int c = i & 15; int nk = i >> 4;
        float dv = base[(size_t)nk*CH + c] - mean;
        s = fmaf(dv, dv, s);
    }
    __shared__ float ss[512];
    ss[t] = s;
    __syncthreads();
    for (int st = 256; st > 0; st >>= 1) {
        if (t < st) ss[t] += ss[t+st];
        __syncthreads();
    }
    if (t == 0) d_stats[b][grp][1] = rsqrtf(ss[0]/(float)M + 1e-5f);
}

__global__ void k_proj(const float* __restrict__ gn_g, const float* __restrict__ gn_b,
                       const float* __restrict__ w_proj, const float* __restrict__ b_proj) {
    int nn = blockIdx.x;
    int c  = threadIdx.x;
    int b  = nn >> 11;
    int grp = c >> 4;
    float mean = d_stats[b][grp][0], rstd = d_stats[b][grp][1];
    float gg = gn_g[c], gb = gn_b[c];
    const float* gp = d_g + (size_t)nn*KNN*CH + c;
    float m = -1e30f;
    #pragma unroll
    for (int k = 0; k < KNN; k++) {
        float v = fmaf((gp[k*CH] - mean)*rstd, gg, gb);
        v = (v >= 0.f) ? v : 0.2f*v;
        m = fmaxf(m, v);
    }
    __shared__ float sm[64];
    sm[c] = m;
    __syncthreads();
    float acc = 0.f;
    const float* wr = w_proj + c*64;
    #pragma unroll
    for (int cc = 0; cc < 64; cc++) acc = fmaf(sm[cc], wr[cc], acc);
    d_f[(size_t)nn*CH + c] = acc + b_proj[c];
}

__global__ void k_scatter(const float* __restrict__ pc) {
    int nn = blockIdx.x;
    int c  = threadIdx.x;
    int b  = nn >> 11;
    float mnx = d_params[b][0], mny = d_params[b][1], grid = d_params[b][2];
    float bx = d_params[b][3], by = d_params[b][4];   // already include the +1
    float px = pc[nn*3+0], py = pc[nn*3+1];
    // PROBE: approximate division here too
    float ix = floorf(__fdividef(__fadd_rn(px, -mnx), grid));
    float iy = floorf(__fdividef(__fadd_rn(py, -mny), grid));
    float fv = d_f[(size_t)nn*CH + c];
    float* rb = d_res + (size_t)b*NPIX*CH + c;
    #pragma unroll
    for (int k = 0; k < 9; k++) {
        float dx = ix + c_off9x[k] + bx;   // exact integers
        float dy = iy + c_off9y[k] + by;
        dx += (dx < 0.f ? 1.f : 0.f) - (dx > (float)(OBJ-1) ? 1.f : 0.f);
        dy += (dy < 0.f ? 1.f : 0.f) - (dy > (float)(OBJ-1) ? 1.f : 0.f);
        int lin = (int)(dx*(float)OBJ + dy);
        atomicAdd(rb + (size_t)lin*CH, fv);
    }
}

__global__ void k_wprep(const float* __restrict__ w1, const float* __restrict__ w2) {
    int i = blockIdx.x*256 + threadIdx.x;
    if (i >= 2*36864) return;
    int which = i / 36864; int r = i - which*36864;
    int o = r / 576; int rem = r - o*576;
    int ci = rem / 9; int tap = rem - ci*9;
    const float* w = which ? w2 : w1;
    d_wt[which][tap][ci][o] = w[r];
}

__global__ void __launch_bounds__(256)
k_conv(int which, const float* __restrict__ gam, const float* __restrict__ bet) {
    extern __shared__ float smem[];
    float* s_in = smem;
    float* s_w  = smem + 324*CSTR;
    const float* in    = which ? d_h1 : d_res;
    float*       outp  = which ? d_h2 : d_h1;
    const float* resid = which ? d_res : nullptr;
    const float* wt    = &d_wt[which][0][0][0];

    int b  = blockIdx.z;
    int y0 = blockIdx.y*16, x0 = blockIdx.x*16;
    int t  = threadIdx.x;
    const float* inb = in + (size_t)b*NPIX*CH;

    for (int e = t; e < 324*16; e += 256) {
        int pix = e >> 4; int c4 = (e & 15) << 2;
        int yy = y0 + (pix/18) - 1, xx = x0 + (pix%18) - 1;
        float4 v = make_float4(0.f,0.f,0.f,0.f);
        if (yy >= 0 && yy < OBJ && xx >= 0 && xx < OBJ)
            v = *(const float4*)(inb + ((size_t)yy*OBJ + xx)*CH + c4);
        float* d = s_in + pix*CSTR + c4;
        d[0]=v.x; d[1]=v.y; d[2]=v.z; d[3]=v.w;
    }

    int cb = (t & 7) * 8;
    int pg = t >> 3;
    int boff[8];
    #pragma unroll
    for (int i = 0; i < 8; i++) {
        int p = pg*8 + i;
        boff[i] = (((p>>4)+1)*18 + ((p&15)+1))*CSTR;
    }

    float acc[8][8];
    #pragma unroll
    for (int i = 0; i < 8; i++)
        #pragma unroll
        for (int j = 0; j < 8; j++) acc[i][j] = 0.f;

    #pragma unroll 1
    for (int tap = 0; tap < 9; tap++) {
        __syncthreads();
        for (int e = t; e < 4096; e += 256) s_w[e] = wt[tap*4096 + e];
        __syncthreads();
        int dy = tap/3 - 1, dx = tap - (tap/3)*3 - 1;
        int toff = (dy*18 + dx)*CSTR;
        #pragma unroll 4
        for (int ci = 0; ci < 64; ci++) {
            float4 wa = *(float4*)(s_w + ci*64 + cb);
            float4 wb2 = *(float4*)(s_w + ci*64 + cb + 4);
            float wv[8] = {wa.x,wa.y,wa.z,wa.w, wb2.x,wb2.y,wb2.z,wb2.w};
            #pragma unroll
            for (int i = 0; i < 8; i++) {
                float iv = s_in[boff[i] + toff + ci];
                #pragma unroll
                for (int j = 0; j < 8; j++) acc[i][j] = fmaf(iv, wv[j], acc[i][j]);
            }
        }
    }

    float gm[8], bt[8];
    #pragma unroll
    for (int j = 0; j < 8; j++) { gm[j] = gam[cb+j]; bt[j] = bet[cb+j]; }
    #pragma unroll
    for (int i = 0; i < 8; i++) {
        int p = pg*8 + i;
        size_t gi = ((size_t)b*NPIX + (size_t)(y0+(p>>4))*OBJ + (x0+(p&15)))*CH + cb;
        float v[8];
        #pragma unroll
        for (int j = 0; j < 8; j++) v[j] = fmaf(acc[i][j], gm[j], bt[j]);
        if (resid) {
            float4 r0 = *(const float4*)(resid + gi);
            float4 r1 = *(const float4*)(resid + gi + 4);
            v[0]+=r0.x; v[1]+=r0.y; v[2]+=r0.z; v[3]+=r0.w;
            v[4]+=r1.x; v[5]+=r1.y; v[6]+=r1.z; v[7]+=r1.w;
        }
        #pragma unroll
        for (int j = 0; j < 8; j++) v[j] = fmaxf(v[j], 0.f);
        *(float4*)(outp + gi)     = make_float4(v[0],v[1],v[2],v[3]);
        *(float4*)(outp + gi + 4) = make_float4(v[4],v[5],v[6],v[7]);
    }
}

__global__ void __launch_bounds__(64)
k_final(const float* __restrict__ wb, const float* __restrict__ bbv,
        const float* __restrict__ wi, const float* __restrict__ biv,
        float* __restrict__ out) {
    __shared__ float s_h[64*64];
    __shared__ float s_wb[64*64];
    __shared__ float s_wi[192];
    __shared__ float s_bb[64];
    int t = threadIdx.x;
    int pix = blockIdx.x*64 + t;

    for (int e = t; e < 4096; e += 64) {
        int o = e >> 6, c = e & 63;
        s_wb[c*64 + o] = wb[e];
    }
    for (int e = t; e < 192; e += 64) s_wi[e] = wi[e];
    if (t < 64) s_bb[t] = bbv[t];
    const float4* h = (const float4*)(d_h2 + (size_t)pix*CH);
    #pragma unroll
    for (int c4 = 0; c4 < 16; c4++) {
        float4 v = h[c4];
        s_h[(c4*4+0)*64 + t] = v.x;
        s_h[(c4*4+1)*64 + t] = v.y;
        s_h[(c4*4+2)*64 + t] = v.z;
        s_h[(c4*4+3)*64 + t] = v.w;
    }
    __syncthreads();

    float h1t[64];
    #pragma unroll
    for (int ob = 0; ob < 8; ob++) {
        float acc[8];
        #pragma unroll
        for (int j = 0; j < 8; j++) acc[j] = 0.f;
        for (int c = 0; c < 64; c++) {
            float hv = s_h[c*64 + t];
            float4 w0 = *(const float4*)(s_wb + c*64 + ob*8);
            float4 w1 = *(const float4*)(s_wb + c*64 + ob*8 + 4);
            acc[0] = fmaf(hv, w0.x, acc[0]); acc[1] = fmaf(hv, w0.y, acc[1]);
            acc[2] = fmaf(hv, w0.z, acc[2]); acc[3] = fmaf(hv, w0.w, acc[3]);
            acc[4] = fmaf(hv, w1.x, acc[4]); acc[5] = fmaf(hv, w1.y, acc[5]);
            acc[6] = fmaf(hv, w1.z, acc[6]); acc[7] = fmaf(hv, w1.w, acc[7]);
        }
        #pragma unroll
        for (int j = 0; j < 8; j++) h1t[ob*8+j] = acc[j] + s_bb[ob*8+j];
    }

    float a[3] = {0.f, 0.f, 0.f};
    #pragma unroll
    for (int c = 0; c < 64; c++) {
        float hv = h1t[c];
        a[0] = fmaf(hv, s_wi[c],       a[0]);
        a[1] = fmaf(hv, s_wi[64 + c],  a[1]);
        a[2] = fmaf(hv, s_wi[128 + c], a[2]);
    }
    int b = pix / NPIX; int p = pix - b*NPIX;
    const float mn[3]  = {0.485f, 0.456f, 0.406f};
    const float sd[3]  = {0.229f, 0.224f, 0.225f};
    #pragma unroll
    for (int j = 0; j < 3; j++) {
        float pre = a[j] + biv[j];
        float s = 1.f/(1.f + expf(-pre));
        out[((size_t)b*3 + j)*NPIX + p] = (s - mn[j])/sd[j];
    }
}

extern "C" void kernel_launch(void* const* d_in, const int* in_sizes, int n_in,
                              void* d_out, int out_size) {
    (void)in_sizes; (void)n_in; (void)out_size;
    const float* pc       = (const float*)d_in[0];
    const float* w_in     = (const float*)d_in[1];
    const float* b_in     = (const float*)d_in[2];
    const float* w_graph  = (const float*)d_in[3];
    const float* gn_g     = (const float*)d_in[4];
    const float* gn_b     = (const float*)d_in[5];
    const float* w_proj   = (const float*)d_in[6];
    const float* b_proj   = (const float*)d_in[7];
    const float* bb_w1    = (const float*)d_in[8];
    const float* bb_g1    = (const float*)d_in[9];
    const float* bb_b1    = (const float*)d_in[10];
    const float* bb_w2    = (const float*)d_in[11];
    const float* bb_g2    = (const float*)d_in[12];
    const float* bb_b2    = (const float*)d_in[13];
    const float* w_blkout = (const float*)d_in[14];
    const float* b_blkout = (const float*)d_in[15];
    const float* w_img    = (const float*)d_in[16];
    const float* b_img    = (const float*)d_in[17];
    float* out = (float*)d_out;

    cudaFuncSetAttribute(k_conv, cudaFuncAttributeMaxDynamicSharedMemorySize, CONV_SMEM_BYTES);

    k_zero<<<(BB*NPIX*CH/4 + 255)/256, 256>>>();
    k_params<<<BB, 256>>>(pc);
    k_f0<<<(BB*NN_ + 255)/256, 256>>>(pc, w_in, b_in);
    k_knn<<<dim3(NN_/256, BB), 256>>>(pc);
    k_graph<<<(BB*NN_*KNN*CH + 255)/256, 256>>>(w_graph);
    k_mean<<<BB*4, 512>>>();
    k_var<<<BB*4, 512>>>();
    k_proj<<<BB*NN_, 64>>>(gn_g, gn_b, w_proj, b_proj);
    k_scatter<<<BB*NN_, 64>>>(pc);
    k_wprep<<<(2*36864 + 255)/256, 256>>>(bb_w1, bb_w2);
    k_conv<<<dim3(14,14,BB), 256, CONV_SMEM_BYTES>>>(0, bb_g1, bb_b1);
    k_conv<<<dim3(14,14,BB), 256, CONV_SMEM_BYTES>>>(1, bb_g2, bb_b2);
    k_final<<<(BB*NPIX)/64, 64>>>(w_blkout, b_blkout, w_img, b_img, out);
}

// round 13
// speedup vs baseline: 1.3648x; 1.3648x over previous
#include <cuda_runtime.h>
#include <math.h>

#define OBJ   224
#define NPIX  (OBJ*OBJ)
#define BB    8
#define NN_   2048
#define KNN   8
#define CH    64
#define WSTR  65
#define CONV_SMEM_FLOATS (324*65 + 64*WSTR)
#define CONV_SMEM_BYTES  (CONV_SMEM_FLOATS*4)

// TF32 operand rounding (mma.sync tf32 input quantization)
__device__ __forceinline__ float tf32r(float x) {
    unsigned u;
    asm("cvt.rna.tf32.f32 %0, %1;" : "=r"(u) : "f"(x));
    return __uint_as_float(u);
}

__device__ float d_params[BB][6];
__device__ float d_f0[BB*NN_*8];
__device__ float d_sq[BB*NN_];
__device__ int   d_knnidx[BB*NN_*KNN];
__device__ float d_g[BB*NN_*KNN*CH];
__device__ float d_stats[BB][4][2];
__device__ float d_f[BB*NN_*CH];
__device__ float d_res[BB*NPIX*CH];
__device__ float d_h1[BB*NPIX*CH];
__device__ float d_h2[BB*NPIX*CH];
__device__ float d_wt[2][9][64][64];       // [tap][ci][o], tf32-rounded
__constant__ float c_off9x[9] = {-1.f,-1.f,-1.f, 0.f,0.f,0.f, 1.f,1.f,1.f};
__constant__ float c_off9y[9] = {-1.f, 0.f, 1.f,-1.f,0.f,1.f,-1.f,0.f,1.f};

__global__ void k_zero() {
    size_t i = (size_t)blockIdx.x*blockDim.x + threadIdx.x;
    const size_t n4 = (size_t)BB*NPIX*CH/4;
    if (i < n4) ((float4*)d_res)[i] = make_float4(0.f,0.f,0.f,0.f);
}

__global__ void k_params(const float* __restrict__ pc) {
    int b = blockIdx.x, t = threadIdx.x;
    float mnx=1e30f, mxx=-1e30f, mny=1e30f, mxy=-1e30f;
    for (int n = t; n < NN_; n += 256) {
        float x = pc[(b*NN_+n)*3+0];
        float y = pc[(b*NN_+n)*3+1];
        mnx=fminf(mnx,x); mxx=fmaxf(mxx,x);
        mny=fminf(mny,y); mxy=fmaxf(mxy,y);
    }
    __shared__ float s0[256], s1[256], s2[256], s3[256];
    s0[t]=mnx; s1[t]=mxx; s2[t]=mny; s3[t]=mxy;
    __syncthreads();
    for (int st=128; st>0; st>>=1) {
        if (t < st) {
            s0[t]=fminf(s0[t],s0[t+st]); s1[t]=fmaxf(s1[t],s1[t+st]);
            s2[t]=fminf(s2[t],s2[t+st]); s3[t]=fmaxf(s3[t],s3[t+st]);
        }
        __syncthreads();
    }
    if (t == 0) {
        float rx = __fadd_rn(s1[0], -s0[0]);
        float ry = __fadd_rn(s3[0], -s2[0]);
        float grid = __fdividef(fmaxf(rx, ry), (float)(OBJ-3));
        float imx = floorf(__fdividef(rx, grid));
        float imy = floorf(__fdividef(ry, grid));
        float cx = floorf((imx + 2.0f) * 0.5f);
        float cy = floorf((imy + 2.0f) * 0.5f);
        float offx = (float)(OBJ/2) - cx - 1.0f;
        float offy = (float)(OBJ/2) - cy - 1.0f;
        d_params[b][0]=s0[0]; d_params[b][1]=s2[0]; d_params[b][2]=grid;
        d_params[b][3]=offx + 1.0f;
        d_params[b][4]=offy + 1.0f;
    }
}

__global__ void k_f0(const float* __restrict__ pc, const float* __restrict__ w_in,
                     const float* __restrict__ b_in) {
    int i = blockIdx.x*256 + threadIdx.x;
    if (i >= BB*NN_) return;
    float x = pc[i*3+0], y = pc[i*3+1], z = pc[i*3+2];
    d_sq[i] = __fadd_rn(__fadd_rn(__fmul_rn(x,x), __fmul_rn(y,y)), __fmul_rn(z,z));
    #pragma unroll
    for (int o = 0; o < 8; o++) {
        float a = 0.f;
        a = fmaf(x, w_in[o*3+0], a);
        a = fmaf(y, w_in[o*3+1], a);
        a = fmaf(z, w_in[o*3+2], a);
        d_f0[i*8 + o] = a + b_in[o];
    }
}

// KNN: identical per-thread math & global ascending candidate order; 4x more blocks.
__global__ void k_knn(const float* __restrict__ pc) {
    int b = blockIdx.y;
    int q = blockIdx.x*64 + threadIdx.x;
    const float* P = pc + (size_t)b*NN_*3;
    float qx = P[q*3+0], qy = P[q*3+1], qz = P[q*3+2];
    float qsq = d_sq[b*NN_ + q];
    __shared__ float4 sp[64];
    float bd[8]; int bi[8];
    #pragma unroll
    for (int k = 0; k < 8; k++) { bd[k] = 3.4e38f; bi[k] = 0; }
    for (int t0 = 0; t0 < NN_; t0 += 64) {
        int j = t0 + threadIdx.x;
        sp[threadIdx.x] = make_float4(P[j*3+0], P[j*3+1], P[j*3+2], d_sq[b*NN_ + j]);
        __syncthreads();
        for (int jj = 0; jj < 64; jj++) {
            float4 c = sp[jj];
            float dot = fmaf(qz, c.z, fmaf(qy, c.y, __fmul_rn(qx, c.x)));
            float tt  = __fadd_rn(qsq, c.w);
            float dd  = __fadd_rn(tt, -__fmul_rn(2.0f, dot));
            if (dd < bd[7]) {
                float cd = dd; int ci = t0 + jj;
                #pragma unroll
                for (int k = 0; k < 8; k++) {
                    if (cd < bd[k]) {
                        float td = bd[k]; int ti = bi[k];
                        bd[k] = cd; bi[k] = ci;
                        cd = td; ci = ti;
                    }
                }
            }
        }
        __syncthreads();
    }
    #pragma unroll
    for (int k = 0; k < 8; k++) d_knnidx[(b*NN_ + q)*KNN + k] = bi[k];
}

__global__ void k_graph(const float* __restrict__ wg) {
    int gid = blockIdx.x*256 + threadIdx.x;
    if (gid >= BB*NN_*KNN*CH) return;
    int o  = gid & 63;
    int k  = (gid >> 6) & 7;
    int nn = gid >> 9;
    int b  = nn >> 11;
    int nbr = d_knnidx[nn*KNN + k];
    const float* fq = d_f0 + nn*8;
    const float* fn = d_f0 + (b*NN_ + nbr)*8;
    const float* w  = wg + o*16;
    float acc = 0.f;
    #pragma unroll
    for (int c = 0; c < 8; c++)
        acc = fmaf(__fadd_rn(fn[c], -fq[c]), w[c], acc);
    #pragma unroll
    for (int c = 0; c < 8; c++)
        acc = fmaf(fq[c], w[8+c], acc);
    d_g[gid] = acc;
}

__global__ void k_mean() {
    int bg = blockIdx.x; int b = bg >> 2, grp = bg & 3;
    int t = threadIdx.x;
    const float* base = d_g + (size_t)b*NN_*KNN*CH + grp*16;
    float s = 0.f;
    const int M = NN_*KNN*16;
    for (int i = t; i < M; i += 512) {
        int c = i & 15; int nk = i >> 4;
        s += base[(size_t)nk*CH + c];
    }
    __shared__ float ss[512];
    ss[t] = s;
    __syncthreads();
    for (int st = 256; st > 0; st >>= 1) {
        if (t < st) ss[t] += ss[t+st];
        __syncthreads();
    }
    if (t == 0) d_stats[b][grp][0] = ss[0] / (float)M;
}

__global__ void k_var() {
    int bg = blockIdx.x; int b = bg >> 2, grp = bg & 3;
    int t = threadIdx.x;
    const float* base = d_g + (size_t)b*NN_*KNN*CH + grp*16;
    float mean = d_stats[b][grp][0];
    float s = 0.f;
    const int M = NN_*KNN*16;
    for (int i = t; i < M; i += 512) {
        int c = i & 15; int nk = i >> 4;
        float dv = base[(size_t)nk*CH + c] - mean;
        s = fmaf(dv, dv, s);
    }
    __shared__ float ss[512];
    ss[t] = s;
    __syncthreads();
    for (int st = 256; st > 0; st >>= 1) {
        if (t < st) ss[t] += ss[t+st];
        __syncthreads();
    }
    if (t == 0) d_stats[b][grp][1] = rsqrtf(ss[0]/(float)M + 1e-5f);
}

__global__ void k_proj(const float* __restrict__ gn_g, const float* __restrict__ gn_b,
                       const float* __restrict__ w_proj, const float* __restrict__ b_proj) {
    int nn = blockIdx.x;
    int c  = threadIdx.x;
    int b  = nn >> 11;
    int grp = c >> 4;
    float mean = d_stats[b][grp][0], rstd = d_stats[b][grp][1];
    float gg = gn_g[c], gb = gn_b[c];
    const float* gp = d_g + (size_t)nn*KNN*CH + c;
    float m = -1e30f;
    #pragma unroll
    for (int k = 0; k < KNN; k++) {
        float v = fmaf((gp[k*CH] - mean)*rstd, gg, gb);
        v = (v >= 0.f) ? v : 0.2f*v;
        m = fmaxf(m, v);
    }
    __shared__ float sm[64];
    sm[c] = m;
    __syncthreads();
    float acc = 0.f;
    const float* wr = w_proj + c*64;
    #pragma unroll
    for (int cc = 0; cc < 64; cc++) acc = fmaf(sm[cc], wr[cc], acc);
    d_f[(size_t)nn*CH + c] = acc + b_proj[c];
}

__global__ void k_scatter(const float* __restrict__ pc) {
    int nn = blockIdx.x;
    int c  = threadIdx.x;
    int b  = nn >> 11;
    float mnx = d_params[b][0], mny = d_params[b][1], grid = d_params[b][2];
    float bx = d_params[b][3], by = d_params[b][4];
    float px = pc[nn*3+0], py = pc[nn*3+1];
    float ix = floorf(__fdividef(__fadd_rn(px, -mnx), grid));
    float iy = floorf(__fdividef(__fadd_rn(py, -mny), grid));
    float fv = d_f[(size_t)nn*CH + c];
    float* rb = d_res + (size_t)b*NPIX*CH + c;
    #pragma unroll
    for (int k = 0; k < 9; k++) {
        float dx = ix + c_off9x[k] + bx;
        float dy = iy + c_off9y[k] + by;
        dx += (dx < 0.f ? 1.f : 0.f) - (dx > (float)(OBJ-1) ? 1.f : 0.f);
        dy += (dy < 0.f ? 1.f : 0.f) - (dy > (float)(OBJ-1) ? 1.f : 0.f);
        int lin = (int)(dx*(float)OBJ + dy);
        atomicAdd(rb + (size_t)lin*CH, fv);
    }
}

// weights -> [tap][ci][o], tf32-rounded (mma operand)
__global__ void k_wprep(const float* __restrict__ w1, const float* __restrict__ w2) {
    int i = blockIdx.x*256 + threadIdx.x;
    if (i >= 2*36864) return;
    int which = i / 36864; int r = i - which*36864;
    int o = r / 576; int rem = r - o*576;
    int ci = rem / 9; int tap = rem - ci*9;
    const float* w = which ? w2 : w1;
    d_wt[which][tap][ci][o] = tf32r(w[r]);
}

// ---------------- 3x3 conv via TF32 mma.sync (implicit GEMM), fp32 accum ----------------
// CTA: 16x16 pixel tile, 8 warps; warp: 32 pixels (2 tile rows) x 64 out-ch.
__global__ void __launch_bounds__(256, 1)
k_conv_mma(int which, const float* __restrict__ gam, const float* __restrict__ bet) {
    extern __shared__ float smem[];
    float* s_in = smem;                 // [324 px][65] tf32-rounded input tile
    float* s_w  = smem + 324*65;        // [64 ci][WSTR] current tap weights
    const float* in    = which ? d_h1 : d_res;
    float*       outp  = which ? d_h2 : d_h1;
    const float* resid = which ? d_res : nullptr;
    const float* wt    = &d_wt[which][0][0][0];

    int b  = blockIdx.z;
    int y0 = blockIdx.y*16, x0 = blockIdx.x*16;
    int t  = threadIdx.x;
    int w  = t >> 5, l = t & 31;
    const float* inb = in + (size_t)b*NPIX*CH;

    // stage 18x18x64 halo tile, tf32-rounded (gemm operand)
    for (int e = t; e < 324*16; e += 256) {
        int pix = e >> 4; int c4 = (e & 15) << 2;
        int yy = y0 + (pix/18) - 1, xx = x0 + (pix%18) - 1;
        float4 v = make_float4(0.f,0.f,0.f,0.f);
        if (yy >= 0 && yy < OBJ && xx >= 0 && xx < OBJ)
            v = *(const float4*)(inb + ((size_t)yy*OBJ + xx)*CH + c4);
        float* d = s_in + pix*65 + c4;
        d[0]=tf32r(v.x); d[1]=tf32r(v.y); d[2]=tf32r(v.z); d[3]=tf32r(v.w);
    }

    float acc[2][8][4];
    #pragma unroll
    for (int mt = 0; mt < 2; mt++)
        #pragma unroll
        for (int n = 0; n < 8; n++)
            #pragma unroll
            for (int j = 0; j < 4; j++) acc[mt][n][j] = 0.f;

    #pragma unroll 1
    for (int tap = 0; tap < 9; tap++) {
        __syncthreads();
        for (int e = t; e < 4096; e += 256) {
            int ci = e >> 6, o = e & 63;
            s_w[ci*WSTR + o] = wt[tap*4096 + e];
        }
        __syncthreads();
        int dy  = tap/3 - 1;
        int dxo = tap - (tap/3)*3 - 1;
        int pb0 = (2*w + 1 + dy)*18 + 1 + dxo;   // mt=0 base pixel (tx=0)

        #pragma unroll 1
        for (int k8 = 0; k8 < 8; k8++) {
            int k0 = k8*8;
            // B fragments: B[k][n] = s_w[k][n], col-major frag
            unsigned bf0[8], bf1[8];
            const float* wp = s_w + (k0 + (l & 3))*WSTR + (l >> 2);
            #pragma unroll
            for (int n = 0; n < 8; n++) {
                bf0[n] = __float_as_uint(wp[n*8]);
                bf1[n] = __float_as_uint(wp[4*WSTR + n*8]);
            }
            #pragma unroll
            for (int mt = 0; mt < 2; mt++) {
                const float* ar0 = s_in + (pb0 + mt*18 + (l >> 2))*65 + k0 + (l & 3);
                const float* ar1 = ar0 + 8*65;
                unsigned a0 = __float_as_uint(ar0[0]);
                unsigned a1 = __float_as_uint(ar1[0]);
                unsigned a2 = __float_as_uint(ar0[4]);
                unsigned a3 = __float_as_uint(ar1[4]);
                #pragma unroll
                for (int n = 0; n < 8; n++) {
                    asm volatile(
                        "mma.sync.aligned.m16n8k8.row.col.f32.tf32.tf32.f32 "
                        "{%0,%1,%2,%3}, {%4,%5,%6,%7}, {%8,%9}, {%0,%1,%2,%3};\n"
                        : "+f"(acc[mt][n][0]), "+f"(acc[mt][n][1]),
                          "+f"(acc[mt][n][2]), "+f"(acc[mt][n][3])
                        : "r"(a0), "r"(a1), "r"(a2), "r"(a3),
                          "r"(bf0[n]), "r"(bf1[n]));
                }
            }
        }
    }

    // epilogue: BN scale/shift (+residual) + ReLU, float2 stores
    int ch0 = 2*(l & 3);
    #pragma unroll
    for (int mt = 0; mt < 2; mt++) {
        int y = y0 + 2*w + mt;
        #pragma unroll
        for (int half = 0; half < 2; half++) {
            int x = x0 + (l >> 2) + half*8;
            size_t gbase = ((size_t)b*NPIX + (size_t)y*OBJ + x)*CH;
            #pragma unroll
            for (int n = 0; n < 8; n++) {
                int ch = n*8 + ch0;
                float v0 = fmaf(acc[mt][n][half*2+0], gam[ch],   bet[ch]);
                float v1 = fmaf(acc[mt][n][half*2+1], gam[ch+1], bet[ch+1]);
                if (resid) {
                    float2 rr = *(const float2*)(resid + gbase + ch);
                    v0 += rr.x; v1 += rr.y;
                }
                v0 = fmaxf(v0, 0.f); v1 = fmaxf(v1, 0.f);
                *(float2*)(outp + gbase + ch) = make_float2(v0, v1);
            }
        }
    }
}

__global__ void __launch_bounds__(64)
k_final(const float* __restrict__ wb, const float* __restrict__ bbv,
        const float* __restrict__ wi, const float* __restrict__ biv,
        float* __restrict__ out) {
    __shared__ float s_h[64*64];
    __shared__ float s_wb[64*64];
    __shared__ float s_wi[192];
    __shared__ float s_bb[64];
    int t = threadIdx.x;
    int pix = blockIdx.x*64 + t;

    for (int e = t; e < 4096; e += 64) {
        int o = e >> 6, c = e & 63;
        s_wb[c*64 + o] = wb[e];
    }
    for (int e = t; e < 192; e += 64) s_wi[e] = wi[e];
    if (t < 64) s_bb[t] = bbv[t];
    const float4* h = (const float4*)(d_h2 + (size_t)pix*CH);
    #pragma unroll
    for (int c4 = 0; c4 < 16; c4++) {
        float4 v = h[c4];
        s_h[(c4*4+0)*64 + t] = v.x;
        s_h[(c4*4+1)*64 + t] = v.y;
        s_h[(c4*4+2)*64 + t] = v.z;
        s_h[(c4*4+3)*64 + t] = v.w;
    }
    __syncthreads();

    float h1t[64];
    #pragma unroll
    for (int ob = 0; ob < 8; ob++) {
        float acc[8];
        #pragma unroll
        for (int j = 0; j < 8; j++) acc[j] = 0.f;
        for (int c = 0; c < 64; c++) {
            float hv = s_h[c*64 + t];
            float4 w0 = *(const float4*)(s_wb + c*64 + ob*8);
            float4 w1 = *(const float4*)(s_wb + c*64 + ob*8 + 4);
            acc[0] = fmaf(hv, w0.x, acc[0]); acc[1] = fmaf(hv, w0.y, acc[1]);
            acc[2] = fmaf(hv, w0.z, acc[2]); acc[3] = fmaf(hv, w0.w, acc[3]);
            acc[4] = fmaf(hv, w1.x, acc[4]); acc[5] = fmaf(hv, w1.y, acc[5]);
            acc[6] = fmaf(hv, w1.z, acc[6]); acc[7] = fmaf(hv, w1.w, acc[7]);
        }
        #pragma unroll
        for (int j = 0; j < 8; j++) h1t[ob*8+j] = acc[j] + s_bb[ob*8+j];
    }

    float a[3] = {0.f, 0.f, 0.f};
    #pragma unroll
    for (int c = 0; c < 64; c++) {
        float hv = h1t[c];
        a[0] = fmaf(hv, s_wi[c],       a[0]);
        a[1] = fmaf(hv, s_wi[64 + c],  a[1]);
        a[2] = fmaf(hv, s_wi[128 + c], a[2]);
    }
    int b = pix / NPIX; int p = pix - b*NPIX;
    const float mn[3]  = {0.485f, 0.456f, 0.406f};
    const float sd[3]  = {0.229f, 0.224f, 0.225f};
    #pragma unroll
    for (int j = 0; j < 3; j++) {
        float pre = a[j] + biv[j];
        float s = 1.f/(1.f + expf(-pre));
        out[((size_t)b*3 + j)*NPIX + p] = (s - mn[j])/sd[j];
    }
}

extern "C" void kernel_launch(void* const* d_in, const int* in_sizes, int n_in,
                              void* d_out, int out_size) {
    (void)in_sizes; (void)n_in; (void)out_size;
    const float* pc       = (const float*)d_in[0];
    const float* w_in     = (const float*)d_in[1];
    const float* b_in     = (const float*)d_in[2];
    const float* w_graph  = (const float*)d_in[3];
    const float* gn_g     = (const float*)d_in[4];
    const float* gn_b     = (const float*)d_in[5];
    const float* w_proj   = (const float*)d_in[6];
    const float* b_proj   = (const float*)d_in[7];
    const float* bb_w1    = (const float*)d_in[8];
    const float* bb_g1    = (const float*)d_in[9];
    const float* bb_b1    = (const float*)d_in[10];
    const float* bb_w2    = (const float*)d_in[11];
    const float* bb_g2    = (const float*)d_in[12];
    const float* bb_b2    = (const float*)d_in[13];
    const float* w_blkout = (const float*)d_in[14];
    const float* b_blkout = (const float*)d_in[15];
    const float* w_img    = (const float*)d_in[16];
    const float* b_img    = (const float*)d_in[17];
    float* out = (float*)d_out;

    cudaFuncSetAttribute(k_conv_mma, cudaFuncAttributeMaxDynamicSharedMemorySize, CONV_SMEM_BYTES);

    k_zero<<<(BB*NPIX*CH/4 + 255)/256, 256>>>();
    k_params<<<BB, 256>>>(pc);
    k_f0<<<(BB*NN_ + 255)/256, 256>>>(pc, w_in, b_in);
    k_knn<<<dim3(NN_/64, BB), 64>>>(pc);
    k_graph<<<(BB*NN_*KNN*CH + 255)/256, 256>>>(w_graph);
    k_mean<<<BB*4, 512>>>();
    k_var<<<BB*4, 512>>>();
    k_proj<<<BB*NN_, 64>>>(gn_g, gn_b, w_proj, b_proj);
    k_scatter<<<BB*NN_, 64>>>(pc);
    k_wprep<<<(2*36864 + 255)/256, 256>>>(bb_w1, bb_w2);
    k_conv_mma<<<dim3(14,14,BB), 256, CONV_SMEM_BYTES>>>(0, bb_g1, bb_b1);
    k_conv_mma<<<dim3(14,14,BB), 256, CONV_SMEM_BYTES>>>(1, bb_g2, bb_b2);
    k_final<<<(BB*NPIX)/64, 64>>>(w_blkout, b_blkout, w_img, b_img, out);
}

// round 15
// speedup vs baseline: 1.6533x; 1.2114x over previous
#include <cuda_runtime.h>
#include <math.h>
#include <stdint.h>

#define OBJ   224
#define NPIX  (OBJ*OBJ)
#define BB    8
#define NN_   2048
#define KNN   8
#define CH    64
// conv smem: s_in 324*65 floats + s_wf 8*32*20 floats
#define CONV_SMEM_FLOATS (324*65 + 8*32*20)
#define CONV_SMEM_BYTES  (CONV_SMEM_FLOATS*4)

__device__ __forceinline__ float tf32r(float x) {
    unsigned u;
    asm("cvt.rna.tf32.f32 %0, %1;" : "=r"(u) : "f"(x));
    return __uint_as_float(u);
}

__device__ float d_params[BB][6];
__device__ float d_f0[BB*NN_*8];
__device__ float d_sq[BB*NN_];
__device__ int   d_knnidx[BB*NN_*KNN];
__device__ float d_g[BB*NN_*KNN*CH];
__device__ float d_stats[BB][4][2];
__device__ float d_f[BB*NN_*CH];
__device__ float d_res[BB*NPIX*CH];
__device__ float d_h1[BB*NPIX*CH];
__device__ float d_h2[BB*NPIX*CH];
__device__ float d_wfrag[2][9][8][32][16];   // per-lane mma B fragments, tf32-rounded
__constant__ float c_off9x[9] = {-1.f,-1.f,-1.f, 0.f,0.f,0.f, 1.f,1.f,1.f};
__constant__ float c_off9y[9] = {-1.f, 0.f, 1.f,-1.f,0.f,1.f,-1.f,0.f,1.f};

__global__ void k_zero() {
    size_t i = (size_t)blockIdx.x*blockDim.x + threadIdx.x;
    const size_t n4 = (size_t)BB*NPIX*CH/4;
    if (i < n4) ((float4*)d_res)[i] = make_float4(0.f,0.f,0.f,0.f);
}

__global__ void k_params(const float* __restrict__ pc) {
    int b = blockIdx.x, t = threadIdx.x;
    float mnx=1e30f, mxx=-1e30f, mny=1e30f, mxy=-1e30f;
    for (int n = t; n < NN_; n += 256) {
        float x = pc[(b*NN_+n)*3+0];
        float y = pc[(b*NN_+n)*3+1];
        mnx=fminf(mnx,x); mxx=fmaxf(mxx,x);
        mny=fminf(mny,y); mxy=fmaxf(mxy,y);
    }
    __shared__ float s0[256], s1[256], s2[256], s3[256];
    s0[t]=mnx; s1[t]=mxx; s2[t]=mny; s3[t]=mxy;
    __syncthreads();
    for (int st=128; st>0; st>>=1) {
        if (t < st) {
            s0[t]=fminf(s0[t],s0[t+st]); s1[t]=fmaxf(s1[t],s1[t+st]);
            s2[t]=fminf(s2[t],s2[t+st]); s3[t]=fmaxf(s3[t],s3[t+st]);
        }
        __syncthreads();
    }
    if (t == 0) {
        float rx = __fadd_rn(s1[0], -s0[0]);
        float ry = __fadd_rn(s3[0], -s2[0]);
        float grid = __fdividef(fmaxf(rx, ry), (float)(OBJ-3));
        float imx = floorf(__fdividef(rx, grid));
        float imy = floorf(__fdividef(ry, grid));
        float cx = floorf((imx + 2.0f) * 0.5f);
        float cy = floorf((imy + 2.0f) * 0.5f);
        float offx = (float)(OBJ/2) - cx - 1.0f;
        float offy = (float)(OBJ/2) - cy - 1.0f;
        d_params[b][0]=s0[0]; d_params[b][1]=s2[0]; d_params[b][2]=grid;
        d_params[b][3]=offx + 1.0f;
        d_params[b][4]=offy + 1.0f;
    }
}

__global__ void k_f0(const float* __restrict__ pc, const float* __restrict__ w_in,
                     const float* __restrict__ b_in) {
    int i = blockIdx.x*256 + threadIdx.x;
    if (i >= BB*NN_) return;
    float x = pc[i*3+0], y = pc[i*3+1], z = pc[i*3+2];
    d_sq[i] = __fadd_rn(__fadd_rn(__fmul_rn(x,x), __fmul_rn(y,y)), __fmul_rn(z,z));
    #pragma unroll
    for (int o = 0; o < 8; o++) {
        float a = 0.f;
        a = fmaf(x, w_in[o*3+0], a);
        a = fmaf(y, w_in[o*3+1], a);
        a = fmaf(z, w_in[o*3+2], a);
        d_f0[i*8 + o] = a + b_in[o];
    }
}

// KNN: 8 threads per query; selection is global top-8 under (d, idx) lexicographic
// order — exactly lax.top_k's stable tie behavior, so the neighbor set is identical.
__global__ void __launch_bounds__(256)
k_knn(const float* __restrict__ pc) {
    int b = blockIdx.y;
    int t = threadIdx.x;
    int qg = t >> 3;            // query within block (0..31)
    int s  = t & 7;             // slice (0..7)
    int q  = blockIdx.x*32 + qg;
    const float* P = pc + (size_t)b*NN_*3;
    float qx = P[q*3+0], qy = P[q*3+1], qz = P[q*3+2];
    float qsq = d_sq[b*NN_ + q];
    __shared__ float4 sp[256];
    __shared__ float  smd[256][8];
    __shared__ int    smi[256][8];
    float bd[8]; int bi[8];
    #pragma unroll
    for (int k = 0; k < 8; k++) { bd[k] = 3.4e38f; bi[k] = 0x7FFFFFFF; }
    for (int t0 = 0; t0 < NN_; t0 += 256) {
        int j = t0 + t;
        sp[t] = make_float4(P[j*3+0], P[j*3+1], P[j*3+2], d_sq[b*NN_ + j]);
        __syncthreads();
        for (int jj = s; jj < 256; jj += 8) {
            float4 c = sp[jj];
            float dot = fmaf(qz, c.z, fmaf(qy, c.y, __fmul_rn(qx, c.x)));
            float tt  = __fadd_rn(qsq, c.w);
            float dd  = __fadd_rn(tt, -__fmul_rn(2.0f, dot));
            int ci = t0 + jj;
            if (dd < bd[7] || (dd == bd[7] && ci < bi[7])) {
                float cd = dd;
                #pragma unroll
                for (int k = 0; k < 8; k++) {
                    if (cd < bd[k] || (cd == bd[k] && ci < bi[k])) {
                        float td = bd[k]; int ti = bi[k];
                        bd[k] = cd; bi[k] = ci;
                        cd = td; ci = ti;
                    }
                }
            }
        }
        __syncthreads();
    }
    #pragma unroll
    for (int k = 0; k < 8; k++) { smd[t][k] = bd[k]; smi[t][k] = bi[k]; }
    __syncthreads();
    if (s == 0) {
        float md[8]; int mi[8];
        #pragma unroll
        for (int k = 0; k < 8; k++) { md[k] = 3.4e38f; mi[k] = 0x7FFFFFFF; }
        for (int u = 0; u < 8; u++) {
            #pragma unroll
            for (int k = 0; k < 8; k++) {
                float cd = smd[qg*8+u][k]; int ci = smi[qg*8+u][k];
                if (cd < md[7] || (cd == md[7] && ci < mi[7])) {
                    #pragma unroll
                    for (int kk = 0; kk < 8; kk++) {
                        if (cd < md[kk] || (cd == md[kk] && ci < mi[kk])) {
                            float td = md[kk]; int ti = mi[kk];
                            md[kk] = cd; mi[kk] = ci;
                            cd = td; ci = ti;
                        }
                    }
                }
            }
        }
        #pragma unroll
        for (int k = 0; k < 8; k++) d_knnidx[(b*NN_ + q)*KNN + k] = mi[k];
    }
}

__global__ void k_graph(const float* __restrict__ wg) {
    int gid = blockIdx.x*256 + threadIdx.x;
    if (gid >= BB*NN_*KNN*CH) return;
    int o  = gid & 63;
    int k  = (gid >> 6) & 7;
    int nn = gid >> 9;
    int b  = nn >> 11;
    int nbr = d_knnidx[nn*KNN + k];
    const float* fq = d_f0 + nn*8;
    const float* fn = d_f0 + (b*NN_ + nbr)*8;
    const float* w  = wg + o*16;
    float acc = 0.f;
    #pragma unroll
    for (int c = 0; c < 8; c++)
        acc = fmaf(__fadd_rn(fn[c], -fq[c]), w[c], acc);
    #pragma unroll
    for (int c = 0; c < 8; c++)
        acc = fmaf(fq[c], w[8+c], acc);
    d_g[gid] = acc;
}

__global__ void k_mean() {
    int bg = blockIdx.x; int b = bg >> 2, grp = bg & 3;
    int t = threadIdx.x;
    const float* base = d_g + (size_t)b*NN_*KNN*CH + grp*16;
    float s = 0.f;
    const int M = NN_*KNN*16;
    for (int i = t; i < M; i += 512) {
        int c = i & 15; int nk = i >> 4;
        s += base[(size_t)nk*CH + c];
    }
    __shared__ float ss[512];
    ss[t] = s;
    __syncthreads();
    for (int st = 256; st > 0; st >>= 1) {
        if (t < st) ss[t] += ss[t+st];
        __syncthreads();
    }
    if (t == 0) d_stats[b][grp][0] = ss[0] / (float)M;
}

__global__ void k_var() {
    int bg = blockIdx.x; int b = bg >> 2, grp = bg & 3;
    int t = threadIdx.x;
    const float* base = d_g + (size_t)b*NN_*KNN*CH + grp*16;
    float mean = d_stats[b][grp][0];
    float s = 0.f;
    const int M = NN_*KNN*16;
    for (int i = t; i < M; i += 512) {
        int c = i & 15; int nk = i >> 4;
        float dv = base[(size_t)nk*CH + c] - mean;
        s = fmaf(dv, dv, s);
    }
    __shared__ float ss[512];
    ss[t] = s;
    __syncthreads();
    for (int st = 256; st > 0; st >>= 1) {
        if (t < st) ss[t] += ss[t+st];
        __syncthreads();
    }
    if (t == 0) d_stats[b][grp][1] = rsqrtf(ss[0]/(float)M + 1e-5f);
}

__global__ void k_proj(const float* __restrict__ gn_g, const float* __restrict__ gn_b,
                       const float* __restrict__ w_proj, const float* __restrict__ b_proj) {
    int nn = blockIdx.x;
    int c  = threadIdx.x;
    int b  = nn >> 11;
    int grp = c >> 4;
    float mean = d_stats[b][grp][0], rstd = d_stats[b][grp][1];
    float gg = gn_g[c], gb = gn_b[c];
    const float* gp = d_g + (size_t)nn*KNN*CH + c;
    float m = -1e30f;
    #pragma unroll
    for (int k = 0; k < KNN; k++) {
        float v = fmaf((gp[k*CH] - mean)*rstd, gg, gb);
        v = (v >= 0.f) ? v : 0.2f*v;
        m = fmaxf(m, v);
    }
    __shared__ float sm[64];
    sm[c] = m;
    __syncthreads();
    float acc = 0.f;
    const float* wr = w_proj + c*64;
    #pragma unroll
    for (int cc = 0; cc < 64; cc++) acc = fmaf(sm[cc], wr[cc], acc);
    d_f[(size_t)nn*CH + c] = acc + b_proj[c];
}

__global__ void k_scatter(const float* __restrict__ pc) {
    int nn = blockIdx.x;
    int c  = threadIdx.x;
    int b  = nn >> 11;
    float mnx = d_params[b][0], mny = d_params[b][1], grid = d_params[b][2];
    float bx = d_params[b][3], by = d_params[b][4];
    float px = pc[nn*3+0], py = pc[nn*3+1];
    float ix = floorf(__fdividef(__fadd_rn(px, -mnx), grid));
    float iy = floorf(__fdividef(__fadd_rn(py, -mny), grid));
    float fv = d_f[(size_t)nn*CH + c];
    float* rb = d_res + (size_t)b*NPIX*CH + c;
    #pragma unroll
    for (int k = 0; k < 9; k++) {
        float dx = ix + c_off9x[k] + bx;
        float dy = iy + c_off9y[k] + by;
        dx += (dx < 0.f ? 1.f : 0.f) - (dx > (float)(OBJ-1) ? 1.f : 0.f);
        dy += (dy < 0.f ? 1.f : 0.f) - (dy > (float)(OBJ-1) ? 1.f : 0.f);
        int lin = (int)(dx*(float)OBJ + dy);
        atomicAdd(rb + (size_t)lin*CH, fv);
    }
}

// Pack weights directly into per-lane mma B-fragment order:
// d_wfrag[which][tap][k8][lane][j]:  n=j>>1, h=j&1,
//   o = (lane>>2) + 8n, ci = 8*k8 + (lane&3) + 4h, value = tf32r(w[o][ci][tap])
__global__ void k_wprep(const float* __restrict__ w1, const float* __restrict__ w2) {
    int i = blockIdx.x*256 + threadIdx.x;
    if (i >= 2*9*8*32*16) return;
    int which = i / 36864; int r = i - which*36864;
    int tap = r >> 12; int r2 = r & 4095;
    int k8 = r2 >> 9; int r3 = r2 & 511;
    int lane = r3 >> 4; int j = r3 & 15;
    int n = j >> 1, h = j & 1;
    int o  = (lane >> 2) + 8*n;
    int ci = 8*k8 + (lane & 3) + 4*h;
    const float* w = which ? w2 : w1;
    d_wfrag[which][tap][k8][lane][j] = tf32r(w[o*576 + ci*9 + tap]);
}

// ---------------- 3x3 conv via TF32 mma.sync, prepacked B frags, 2 CTAs/SM ----------------
__global__ void __launch_bounds__(256, 2)
k_conv_mma(int which, const float* __restrict__ gam, const float* __restrict__ bet) {
    extern __shared__ float smem[];
    float* s_in = smem;                  // [324 px][65]
    float* s_wf = smem + 324*65;         // [8 k8][32 lane][20] (16 used, pad to 20)
    const float* in    = which ? d_h1 : d_res;
    float*       outp  = which ? d_h2 : d_h1;
    const float* resid = which ? d_res : nullptr;
    const float* wf    = &d_wfrag[which][0][0][0][0];

    int b  = blockIdx.z;
    int y0 = blockIdx.y*16, x0 = blockIdx.x*16;
    int t  = threadIdx.x;
    int w  = t >> 5, l = t & 31;
    const float* inb = in + (size_t)b*NPIX*CH;

    for (int e = t; e < 324*16; e += 256) {
        int pix = e >> 4; int c4 = (e & 15) << 2;
        int yy = y0 + (pix/18) - 1, xx = x0 + (pix%18) - 1;
        float4 v = make_float4(0.f,0.f,0.f,0.f);
        if (yy >= 0 && yy < OBJ && xx >= 0 && xx < OBJ)
            v = *(const float4*)(inb + ((size_t)yy*OBJ + xx)*CH + c4);
        float* d = s_in + pix*65 + c4;
        d[0]=tf32r(v.x); d[1]=tf32r(v.y); d[2]=tf32r(v.z); d[3]=tf32r(v.w);
    }

    float acc[2][8][4];
    #pragma unroll
    for (int mt = 0; mt < 2; mt++)
        #pragma unroll
        for (int n = 0; n < 8; n++)
            #pragma unroll
            for (int j = 0; j < 4; j++) acc[mt][n][j] = 0.f;

    #pragma unroll 1
    for (int tap = 0; tap < 9; tap++) {
        __syncthreads();
        // stage this tap's fragments: 1024 float4s, coalesced
        const float4* src = (const float4*)(wf + tap*4096);
        for (int e = t; e < 1024; e += 256) {
            int k8 = e >> 7; int lane = (e >> 2) & 31; int qv = e & 3;
            *(float4*)(s_wf + (k8*32 + lane)*20 + qv*4) = src[e];
        }
        __syncthreads();
        int dy  = tap/3 - 1;
        int dxo = tap - (tap/3)*3 - 1;
        int pb0 = (2*w + 1 + dy)*18 + 1 + dxo;

        #pragma unroll 1
        for (int k8 = 0; k8 < 8; k8++) {
            int k0 = k8*8;
            const float* fp = s_wf + (k8*32 + l)*20;
            float4 f0 = *(const float4*)(fp);
            float4 f1 = *(const float4*)(fp + 4);
            float4 f2 = *(const float4*)(fp + 8);
            float4 f3 = *(const float4*)(fp + 12);
            unsigned bf[16] = {
                __float_as_uint(f0.x), __float_as_uint(f0.y), __float_as_uint(f0.z), __float_as_uint(f0.w),
                __float_as_uint(f1.x), __float_as_uint(f1.y), __float_as_uint(f1.z), __float_as_uint(f1.w),
                __float_as_uint(f2.x), __float_as_uint(f2.y), __float_as_uint(f2.z), __float_as_uint(f2.w),
                __float_as_uint(f3.x), __float_as_uint(f3.y), __float_as_uint(f3.z), __float_as_uint(f3.w)};
            #pragma unroll
            for (int mt = 0; mt < 2; mt++) {
                const float* ar0 = s_in + (pb0 + mt*18 + (l >> 2))*65 + k0 + (l & 3);
                const float* ar1 = ar0 + 8*65;
                unsigned a0 = __float_as_uint(ar0[0]);
                unsigned a1 = __float_as_uint(ar1[0]);
                unsigned a2 = __float_as_uint(ar0[4]);
                unsigned a3 = __float_as_uint(ar1[4]);
                #pragma unroll
                for (int n = 0; n < 8; n++) {
                    asm volatile(
                        "mma.sync.aligned.m16n8k8.row.col.f32.tf32.tf32.f32 "
                        "{%0,%1,%2,%3}, {%4,%5,%6,%7}, {%8,%9}, {%0,%1,%2,%3};\n"
                        : "+f"(acc[mt][n][0]), "+f"(acc[mt][n][1]),
                          "+f"(acc[mt][n][2]), "+f"(acc[mt][n][3])
                        : "r"(a0), "r"(a1), "r"(a2), "r"(a3),
                          "r"(bf[2*n]), "r"(bf[2*n+1]));
                }
            }
        }
    }

    int ch0 = 2*(l & 3);
    #pragma unroll
    for (int mt = 0; mt < 2; mt++) {
        int y = y0 + 2*w + mt;
        #pragma unroll
        for (int half = 0; half < 2; half++) {
            int x = x0 + (l >> 2) + half*8;
            size_t gbase = ((size_t)b*NPIX + (size_t)y*OBJ + x)*CH;
            #pragma unroll
            for (int n = 0; n < 8; n++) {
                int ch = n*8 + ch0;
                float v0 = fmaf(acc[mt][n][half*2+0], gam[ch],   bet[ch]);
                float v1 = fmaf(acc[mt][n][half*2+1], gam[ch+1], bet[ch+1]);
                if (resid) {
                    float2 rr = *(const float2*)(resid + gbase + ch);
                    v0 += rr.x; v1 += rr.y;
                }
                v0 = fmaxf(v0, 0.f); v1 = fmaxf(v1, 0.f);
                *(float2*)(outp + gbase + ch) = make_float2(v0, v1);
            }
        }
    }
}

__global__ void __launch_bounds__(64)
k_final(const float* __restrict__ wb, const float* __restrict__ bbv,
        const float* __restrict__ wi, const float* __restrict__ biv,
        float* __restrict__ out) {
    __shared__ float s_h[64*64];
    __shared__ float s_wb[64*64];
    __shared__ float s_wi[192];
    __shared__ float s_bb[64];
    int t = threadIdx.x;
    int pix = blockIdx.x*64 + t;

    for (int e = t; e < 4096; e += 64) {
        int o = e >> 6, c = e & 63;
        s_wb[c*64 + o] = wb[e];
    }
    for (int e = t; e < 192; e += 64) s_wi[e] = wi[e];
    if (t < 64) s_bb[t] = bbv[t];
    const float4* h = (const float4*)(d_h2 + (size_t)pix*CH);
    #pragma unroll
    for (int c4 = 0; c4 < 16; c4++) {
        float4 v = h[c4];
        s_h[(c4*4+0)*64 + t] = v.x;
        s_h[(c4*4+1)*64 + t] = v.y;
        s_h[(c4*4+2)*64 + t] = v.z;
        s_h[(c4*4+3)*64 + t] = v.w;
    }
    __syncthreads();

    float h1t[64];
    #pragma unroll
    for (int ob = 0; ob < 8; ob++) {
        float acc[8];
        #pragma unroll
        for (int j = 0; j < 8; j++) acc[j] = 0.f;
        for (int c = 0; c < 64; c++) {
            float hv = s_h[c*64 + t];
            float4 w0 = *(const float4*)(s_wb + c*64 + ob*8);
            float4 w1 = *(const float4*)(s_wb + c*64 + ob*8 + 4);
            acc[0] = fmaf(hv, w0.x, acc[0]); acc[1] = fmaf(hv, w0.y, acc[1]);
            acc[2] = fmaf(hv, w0.z, acc[2]); acc[3] = fmaf(hv, w0.w, acc[3]);
            acc[4] = fmaf(hv, w1.x, acc[4]); acc[5] = fmaf(hv, w1.y, acc[5]);
            acc[6] = fmaf(hv, w1.z, acc[6]); acc[7] = fmaf(hv, w1.w, acc[7]);
        }
        #pragma unroll
        for (int j = 0; j < 8; j++) h1t[ob*8+j] = acc[j] + s_bb[ob*8+j];
    }

    float a[3] = {0.f, 0.f, 0.f};
    #pragma unroll
    for (int c = 0; c < 64; c++) {
        float hv = h1t[c];
        a[0] = fmaf(hv, s_wi[c],       a[0]);
        a[1] = fmaf(hv, s_wi[64 + c],  a[1]);
        a[2] = fmaf(hv, s_wi[128 + c], a[2]);
    }
    int b = pix / NPIX; int p = pix - b*NPIX;
    const float mn[3]  = {0.485f, 0.456f, 0.406f};
    const float sd[3]  = {0.229f, 0.224f, 0.225f};
    #pragma unroll
    for (int j = 0; j < 3; j++) {
        float pre = a[j] + biv[j];
        float s = 1.f/(1.f + expf(-pre));
        out[((size_t)b*3 + j)*NPIX + p] = (s - mn[j])/sd[j];
    }
}

extern "C" void kernel_launch(void* const* d_in, const int* in_sizes, int n_in,
                              void* d_out, int out_size) {
    (void)in_sizes; (void)n_in; (void)out_size;
    const float* pc       = (const float*)d_in[0];
    const float* w_in     = (const float*)d_in[1];
    const float* b_in     = (const float*)d_in[2];
    const float* w_graph  = (const float*)d_in[3];
    const float* gn_g     = (const float*)d_in[4];
    const float* gn_b     = (const float*)d_in[5];
    const float* w_proj   = (const float*)d_in[6];
    const float* b_proj   = (const float*)d_in[7];
    const float* bb_w1    = (const float*)d_in[8];
    const float* bb_g1    = (const float*)d_in[9];
    const float* bb_b1    = (const float*)d_in[10];
    const float* bb_w2    = (const float*)d_in[11];
    const float* bb_g2    = (const float*)d_in[12];
    const float* bb_b2    = (const float*)d_in[13];
    const float* w_blkout = (const float*)d_in[14];
    const float* b_blkout = (const float*)d_in[15];
    const float* w_img    = (const float*)d_in[16];
    const float* b_img    = (const float*)d_in[17];
    float* out = (float*)d_out;

    cudaFuncSetAttribute(k_conv_mma, cudaFuncAttributeMaxDynamicSharedMemorySize, CONV_SMEM_BYTES);

    k_zero<<<(BB*NPIX*CH/4 + 255)/256, 256>>>();
    k_params<<<BB, 256>>>(pc);
    k_f0<<<(BB*NN_ + 255)/256, 256>>>(pc, w_in, b_in);
    k_knn<<<dim3(NN_/32, BB), 256>>>(pc);
    k_graph<<<(BB*NN_*KNN*CH + 255)/256, 256>>>(w_graph);
    k_mean<<<BB*4, 512>>>();
    k_var<<<BB*4, 512>>>();
    k_proj<<<BB*NN_, 64>>>(gn_g, gn_b, w_proj, b_proj);
    k_scatter<<<BB*NN_, 64>>>(pc);
    k_wprep<<<(2*9*8*32*16 + 255)/256, 256>>>(bb_w1, bb_w2);
    k_conv_mma<<<dim3(14,14,BB), 256, CONV_SMEM_BYTES>>>(0, bb_g1, bb_b1);
    k_conv_mma<<<dim3(14,14,BB), 256, CONV_SMEM_BYTES>>>(1, bb_g2, bb_b2);
    k_final<<<(BB*NPIX)/64, 64>>>(w_blkout, b_blkout, w_img, b_img, out);
}

// round 17
// speedup vs baseline: 1.7779x; 1.0754x over previous
#include <cuda_runtime.h>
#include <math.h>
#include <stdint.h>

#define OBJ   224
#define NPIX  (OBJ*OBJ)
#define BB    8
#define NN_   2048
#define KNN   8
#define CH    64
#define ISTR  68     // input tile pixel stride (68 mod 32 = 4 -> conflict-free A LDS)
// conv smem: s_in 324*ISTR floats + s_wf 8*32*20 floats
#define CONV_SMEM_FLOATS (324*ISTR + 8*32*20)
#define CONV_SMEM_BYTES  (CONV_SMEM_FLOATS*4)

__device__ __forceinline__ float tf32r(float x) {
    unsigned u;
    asm("cvt.rna.tf32.f32 %0, %1;" : "=r"(u) : "f"(x));
    return __uint_as_float(u);
}

__device__ float d_params[BB][6];
__device__ float d_f0[BB*NN_*8];
__device__ float d_sq[BB*NN_];
__device__ int   d_knnidx[BB*NN_*KNN];
__device__ float d_g[BB*NN_*KNN*CH];
__device__ float d_stats[BB][4][2];
__device__ float d_f[BB*NN_*CH];
__device__ float d_res[BB*NPIX*CH];
__device__ float d_h1[BB*NPIX*CH];
__device__ float d_h2[BB*NPIX*CH];
__device__ float d_wfrag[2][9][8][32][16];   // per-lane mma B fragments, tf32-rounded
__constant__ float c_off9x[9] = {-1.f,-1.f,-1.f, 0.f,0.f,0.f, 1.f,1.f,1.f};
__constant__ float c_off9y[9] = {-1.f, 0.f, 1.f,-1.f,0.f,1.f,-1.f,0.f,1.f};

__global__ void k_zero() {
    size_t i = (size_t)blockIdx.x*blockDim.x + threadIdx.x;
    const size_t n4 = (size_t)BB*NPIX*CH/4;
    if (i < n4) ((float4*)d_res)[i] = make_float4(0.f,0.f,0.f,0.f);
}

__global__ void k_params(const float* __restrict__ pc) {
    int b = blockIdx.x, t = threadIdx.x;
    float mnx=1e30f, mxx=-1e30f, mny=1e30f, mxy=-1e30f;
    for (int n = t; n < NN_; n += 256) {
        float x = pc[(b*NN_+n)*3+0];
        float y = pc[(b*NN_+n)*3+1];
        mnx=fminf(mnx,x); mxx=fmaxf(mxx,x);
        mny=fminf(mny,y); mxy=fmaxf(mxy,y);
    }
    __shared__ float s0[256], s1[256], s2[256], s3[256];
    s0[t]=mnx; s1[t]=mxx; s2[t]=mny; s3[t]=mxy;
    __syncthreads();
    for (int st=128; st>0; st>>=1) {
        if (t < st) {
            s0[t]=fminf(s0[t],s0[t+st]); s1[t]=fmaxf(s1[t],s1[t+st]);
            s2[t]=fminf(s2[t],s2[t+st]); s3[t]=fmaxf(s3[t],s3[t+st]);
        }
        __syncthreads();
    }
    if (t == 0) {
        float rx = __fadd_rn(s1[0], -s0[0]);
        float ry = __fadd_rn(s3[0], -s2[0]);
        float grid = __fdividef(fmaxf(rx, ry), (float)(OBJ-3));
        float imx = floorf(__fdividef(rx, grid));
        float imy = floorf(__fdividef(ry, grid));
        float cx = floorf((imx + 2.0f) * 0.5f);
        float cy = floorf((imy + 2.0f) * 0.5f);
        float offx = (float)(OBJ/2) - cx - 1.0f;
        float offy = (float)(OBJ/2) - cy - 1.0f;
        d_params[b][0]=s0[0]; d_params[b][1]=s2[0]; d_params[b][2]=grid;
        d_params[b][3]=offx + 1.0f;
        d_params[b][4]=offy + 1.0f;
    }
}

__global__ void k_f0(const float* __restrict__ pc, const float* __restrict__ w_in,
                     const float* __restrict__ b_in) {
    int i = blockIdx.x*256 + threadIdx.x;
    if (i >= BB*NN_) return;
    float x = pc[i*3+0], y = pc[i*3+1], z = pc[i*3+2];
    d_sq[i] = __fadd_rn(__fadd_rn(__fmul_rn(x,x), __fmul_rn(y,y)), __fmul_rn(z,z));
    #pragma unroll
    for (int o = 0; o < 8; o++) {
        float a = 0.f;
        a = fmaf(x, w_in[o*3+0], a);
        a = fmaf(y, w_in[o*3+1], a);
        a = fmaf(z, w_in[o*3+2], a);
        d_f0[i*8 + o] = a + b_in[o];
    }
}

// KNN: 8 threads/query. Within a slice candidates arrive ascending-j, so strict-<
// insertion keeps the lower index on ties (== (d,idx) lexicographic). The 8-way
// merge uses the explicit lexicographic compare. Neighbor set identical to top_k.
__global__ void __launch_bounds__(256)
k_knn(const float* __restrict__ pc) {
    int b = blockIdx.y;
    int t = threadIdx.x;
    int qg = t >> 3;            // query within block (0..31)
    int s  = t & 7;             // slice (0..7)
    int q  = blockIdx.x*32 + qg;
    const float* P = pc + (size_t)b*NN_*3;
    float qx = P[q*3+0], qy = P[q*3+1], qz = P[q*3+2];
    float qsq = d_sq[b*NN_ + q];
    __shared__ float4 sp[256];
    __shared__ float  smd[256][8];
    __shared__ int    smi[256][8];
    float bd[8]; int bi[8];
    #pragma unroll
    for (int k = 0; k < 8; k++) { bd[k] = 3.4e38f; bi[k] = 0x7FFFFFFF; }
    for (int t0 = 0; t0 < NN_; t0 += 256) {
        int j = t0 + t;
        sp[t] = make_float4(P[j*3+0], P[j*3+1], P[j*3+2], d_sq[b*NN_ + j]);
        __syncthreads();
        for (int jj = s; jj < 256; jj += 8) {
            float4 c = sp[jj];
            float dot = fmaf(qz, c.z, fmaf(qy, c.y, __fmul_rn(qx, c.x)));
            float tt  = __fadd_rn(qsq, c.w);
            float dd  = __fadd_rn(tt, -__fmul_rn(2.0f, dot));
            if (dd < bd[7]) {              // strict <: ties keep earlier (lower) index
                float cd = dd; int ci = t0 + jj;
                #pragma unroll
                for (int k = 0; k < 8; k++) {
                    if (cd < bd[k]) {
                        float td = bd[k]; int ti = bi[k];
                        bd[k] = cd; bi[k] = ci;
                        cd = td; ci = ti;
                    }
                }
            }
        }
        __syncthreads();
    }
    #pragma unroll
    for (int k = 0; k < 8; k++) { smd[t][k] = bd[k]; smi[t][k] = bi[k]; }
    __syncthreads();
    if (s == 0) {
        float md[8]; int mi[8];
        #pragma unroll
        for (int k = 0; k < 8; k++) { md[k] = 3.4e38f; mi[k] = 0x7FFFFFFF; }
        for (int u = 0; u < 8; u++) {
            #pragma unroll
            for (int k = 0; k < 8; k++) {
                float cd = smd[qg*8+u][k]; int ci = smi[qg*8+u][k];
                if (cd < md[7] || (cd == md[7] && ci < mi[7])) {
                    #pragma unroll
                    for (int kk = 0; kk < 8; kk++) {
                        if (cd < md[kk] || (cd == md[kk] && ci < mi[kk])) {
                            float td = md[kk]; int ti = mi[kk];
                            md[kk] = cd; mi[kk] = ci;
                            cd = td; ci = ti;
                        }
                    }
                }
            }
        }
        #pragma unroll
        for (int k = 0; k < 8; k++) d_knnidx[(b*NN_ + q)*KNN + k] = mi[k];
    }
}

__global__ void k_graph(const float* __restrict__ wg) {
    int gid = blockIdx.x*256 + threadIdx.x;
    if (gid >= BB*NN_*KNN*CH) return;
    int o  = gid & 63;
    int k  = (gid >> 6) & 7;
    int nn = gid >> 9;
    int b  = nn >> 11;
    int nbr = d_knnidx[nn*KNN + k];
    const float* fq = d_f0 + nn*8;
    const float* fn = d_f0 + (b*NN_ + nbr)*8;
    const float* w  = wg + o*16;
    float acc = 0.f;
    #pragma unroll
    for (int c = 0; c < 8; c++)
        acc = fmaf(__fadd_rn(fn[c], -fq[c]), w[c], acc);
    #pragma unroll
    for (int c = 0; c < 8; c++)
        acc = fmaf(fq[c], w[8+c], acc);
    d_g[gid] = acc;
}

__global__ void k_mean() {
    int bg = blockIdx.x; int b = bg >> 2, grp = bg & 3;
    int t = threadIdx.x;
    const float* base = d_g + (size_t)b*NN_*KNN*CH + grp*16;
    float s = 0.f;
    const int M = NN_*KNN*16;
    for (int i = t; i < M; i += 512) {
        int c = i & 15; int nk = i >> 4;
        s += base[(size_t)nk*CH + c];
    }
    __shared__ float ss[512];
    ss[t] = s;
    __syncthreads();
    for (int st = 256; st > 0; st >>= 1) {
        if (t < st) ss[t] += ss[t+st];
        __syncthreads();
    }
    if (t == 0) d_stats[b][grp][0] = ss[0] / (float)M;
}

__global__ void k_var() {
    int bg = blockIdx.x; int b = bg >> 2, grp = bg & 3;
    int t = threadIdx.x;
    const float* base = d_g + (size_t)b*NN_*KNN*CH + grp*16;
    float mean = d_stats[b][grp][0];
    float s = 0.f;
    const int M = NN_*KNN*16;
    for (int i = t; i < M; i += 512) {
        int c = i & 15; int nk = i >> 4;
        float dv = base[(size_t)nk*CH + c] - mean;
        s = fmaf(dv, dv, s);
    }
    __shared__ float ss[512];
    ss[t] = s;
    __syncthreads();
    for (int st = 256; st > 0; st >>= 1) {
        if (t < st) ss[t] += ss[t+st];
        __syncthreads();
    }
    if (t == 0) d_stats[b][grp][1] = rsqrtf(ss[0]/(float)M + 1e-5f);
}

__global__ void k_proj(const float* __restrict__ gn_g, const float* __restrict__ gn_b,
                       const float* __restrict__ w_proj, const float* __restrict__ b_proj) {
    int nn = blockIdx.x;
    int c  = threadIdx.x;
    int b  = nn >> 11;
    int grp = c >> 4;
    float mean = d_stats[b][grp][0], rstd = d_stats[b][grp][1];
    float gg = gn_g[c], gb = gn_b[c];
    const float* gp = d_g + (size_t)nn*KNN*CH + c;
    float m = -1e30f;
    #pragma unroll
    for (int k = 0; k < KNN; k++) {
        float v = fmaf((gp[k*CH] - mean)*rstd, gg, gb);
        v = (v >= 0.f) ? v : 0.2f*v;
        m = fmaxf(m, v);
    }
    __shared__ float sm[64];
    sm[c] = m;
    __syncthreads();
    float acc = 0.f;
    const float* wr = w_proj + c*64;
    #pragma unroll
    for (int cc = 0; cc < 64; cc++) acc = fmaf(sm[cc], wr[cc], acc);
    d_f[(size_t)nn*CH + c] = acc + b_proj[c];
}

__global__ void k_scatter(const float* __restrict__ pc) {
    int nn = blockIdx.x;
    int c  = threadIdx.x;
    int b  = nn >> 11;
    float mnx = d_params[b][0], mny = d_params[b][1], grid = d_params[b][2];
    float bx = d_params[b][3], by = d_params[b][4];
    float px = pc[nn*3+0], py = pc[nn*3+1];
    float ix = floorf(__fdividef(__fadd_rn(px, -mnx), grid));
    float iy = floorf(__fdividef(__fadd_rn(py, -mny), grid));
    float fv = d_f[(size_t)nn*CH + c];
    float* rb = d_res + (size_t)b*NPIX*CH + c;
    #pragma unroll
    for (int k = 0; k < 9; k++) {
        float dx = ix + c_off9x[k] + bx;
        float dy = iy + c_off9y[k] + by;
        dx += (dx < 0.f ? 1.f : 0.f) - (dx > (float)(OBJ-1) ? 1.f : 0.f);
        dy += (dy < 0.f ? 1.f : 0.f) - (dy > (float)(OBJ-1) ? 1.f : 0.f);
        int lin = (int)(dx*(float)OBJ + dy);
        atomicAdd(rb + (size_t)lin*CH, fv);
    }
}

// Pack weights directly into per-lane mma B-fragment order:
// d_wfrag[which][tap][k8][lane][j]:  n=j>>1, h=j&1,
//   o = (lane>>2) + 8n, ci = 8*k8 + (lane&3) + 4h, value = tf32r(w[o][ci][tap])
__global__ void k_wprep(const float* __restrict__ w1, const float* __restrict__ w2) {
    int i = blockIdx.x*256 + threadIdx.x;
    if (i >= 2*9*8*32*16) return;
    int which = i / 36864; int r = i - which*36864;
    int tap = r >> 12; int r2 = r & 4095;
    int k8 = r2 >> 9; int r3 = r2 & 511;
    int lane = r3 >> 4; int j = r3 & 15;
    int n = j >> 1, h = j & 1;
    int o  = (lane >> 2) + 8*n;
    int ci = 8*k8 + (lane & 3) + 4*h;
    const float* w = which ? w2 : w1;
    d_wfrag[which][tap][k8][lane][j] = tf32r(w[o*576 + ci*9 + tap]);
}

// ---------------- 3x3 conv via TF32 mma.sync, prepacked B frags, 2 CTAs/SM ----------------
__global__ void __launch_bounds__(256, 2)
k_conv_mma(int which, const float* __restrict__ gam, const float* __restrict__ bet) {
    extern __shared__ float smem[];
    float* s_in = smem;                  // [324 px][ISTR]
    float* s_wf = smem + 324*ISTR;       // [8 k8][32 lane][20] (16 used, pad to 20)
    const float* in    = which ? d_h1 : d_res;
    float*       outp  = which ? d_h2 : d_h1;
    const float* resid = which ? d_res : nullptr;
    const float* wf    = &d_wfrag[which][0][0][0][0];

    int b  = blockIdx.z;
    int y0 = blockIdx.y*16, x0 = blockIdx.x*16;
    int t  = threadIdx.x;
    int w  = t >> 5, l = t & 31;
    const float* inb = in + (size_t)b*NPIX*CH;

    for (int e = t; e < 324*16; e += 256) {
        int pix = e >> 4; int c4 = (e & 15) << 2;
        int yy = y0 + (pix/18) - 1, xx = x0 + (pix%18) - 1;
        float4 v = make_float4(0.f,0.f,0.f,0.f);
        if (yy >= 0 && yy < OBJ && xx >= 0 && xx < OBJ)
            v = *(const float4*)(inb + ((size_t)yy*OBJ + xx)*CH + c4);
        float* d = s_in + pix*ISTR + c4;
        d[0]=tf32r(v.x); d[1]=tf32r(v.y); d[2]=tf32r(v.z); d[3]=tf32r(v.w);
    }

    float acc[2][8][4];
    #pragma unroll
    for (int mt = 0; mt < 2; mt++)
        #pragma unroll
        for (int n = 0; n < 8; n++)
            #pragma unroll
            for (int j = 0; j < 4; j++) acc[mt][n][j] = 0.f;

    #pragma unroll 1
    for (int tap = 0; tap < 9; tap++) {
        __syncthreads();
        const float4* src = (const float4*)(wf + tap*4096);
        for (int e = t; e < 1024; e += 256) {
            int k8 = e >> 7; int lane = (e >> 2) & 31; int qv = e & 3;
            *(float4*)(s_wf + (k8*32 + lane)*20 + qv*4) = src[e];
        }
        __syncthreads();
        int dy  = tap/3 - 1;
        int dxo = tap - (tap/3)*3 - 1;
        int pb0 = (2*w + 1 + dy)*18 + 1 + dxo;

        #pragma unroll 1
        for (int k8 = 0; k8 < 8; k8++) {
            int k0 = k8*8;
            const float* fp = s_wf + (k8*32 + l)*20;
            float4 f0 = *(const float4*)(fp);
            float4 f1 = *(const float4*)(fp + 4);
            float4 f2 = *(const float4*)(fp + 8);
            float4 f3 = *(const float4*)(fp + 12);
            unsigned bf[16] = {
                __float_as_uint(f0.x), __float_as_uint(f0.y), __float_as_uint(f0.z), __float_as_uint(f0.w),
                __float_as_uint(f1.x), __float_as_uint(f1.y), __float_as_uint(f1.z), __float_as_uint(f1.w),
                __float_as_uint(f2.x), __float_as_uint(f2.y), __float_as_uint(f2.z), __float_as_uint(f2.w),
                __float_as_uint(f3.x), __float_as_uint(f3.y), __float_as_uint(f3.z), __float_as_uint(f3.w)};
            #pragma unroll
            for (int mt = 0; mt < 2; mt++) {
                const float* ar0 = s_in + (pb0 + mt*18 + (l >> 2))*ISTR + k0 + (l & 3);
                const float* ar1 = ar0 + 8*ISTR;
                unsigned a0 = __float_as_uint(ar0[0]);
                unsigned a1 = __float_as_uint(ar1[0]);
                unsigned a2 = __float_as_uint(ar0[4]);
                unsigned a3 = __float_as_uint(ar1[4]);
                #pragma unroll
                for (int n = 0; n < 8; n++) {
                    asm volatile(
                        "mma.sync.aligned.m16n8k8.row.col.f32.tf32.tf32.f32 "
                        "{%0,%1,%2,%3}, {%4,%5,%6,%7}, {%8,%9}, {%0,%1,%2,%3};\n"
                        : "+f"(acc[mt][n][0]), "+f"(acc[mt][n][1]),
                          "+f"(acc[mt][n][2]), "+f"(acc[mt][n][3])
                        : "r"(a0), "r"(a1), "r"(a2), "r"(a3),
                          "r"(bf[2*n]), "r"(bf[2*n+1]));
                }
            }
        }
    }

    int ch0 = 2*(l & 3);
    #pragma unroll
    for (int mt = 0; mt < 2; mt++) {
        int y = y0 + 2*w + mt;
        #pragma unroll
        for (int half = 0; half < 2; half++) {
            int x = x0 + (l >> 2) + half*8;
            size_t gbase = ((size_t)b*NPIX + (size_t)y*OBJ + x)*CH;
            #pragma unroll
            for (int n = 0; n < 8; n++) {
                int ch = n*8 + ch0;
                float v0 = fmaf(acc[mt][n][half*2+0], gam[ch],   bet[ch]);
                float v1 = fmaf(acc[mt][n][half*2+1], gam[ch+1], bet[ch+1]);
                if (resid) {
                    float2 rr = *(const float2*)(resid + gbase + ch);
                    v0 += rr.x; v1 += rr.y;
                }
                v0 = fmaxf(v0, 0.f); v1 = fmaxf(v1, 0.f);
                *(float2*)(outp + gbase + ch) = make_float2(v0, v1);
            }
        }
    }
}

__global__ void __launch_bounds__(64)
k_final(const float* __restrict__ wb, const float* __restrict__ bbv,
        const float* __restrict__ wi, const float* __restrict__ biv,
        float* __restrict__ out) {
    __shared__ float s_h[64*64];
    __shared__ float s_wb[64*64];
    __shared__ float s_wi[192];
    __shared__ float s_bb[64];
    int t = threadIdx.x;
    int pix = blockIdx.x*64 + t;

    for (int e = t; e < 4096; e += 64) {
        int o = e >> 6, c = e & 63;
        s_wb[c*64 + o] = wb[e];
    }
    for (int e = t; e < 192; e += 64) s_wi[e] = wi[e];
    if (t < 64) s_bb[t] = bbv[t];
    const float4* h = (const float4*)(d_h2 + (size_t)pix*CH);
    #pragma unroll
    for (int c4 = 0; c4 < 16; c4++) {
        float4 v = h[c4];
        s_h[(c4*4+0)*64 + t] = v.x;
        s_h[(c4*4+1)*64 + t] = v.y;
        s_h[(c4*4+2)*64 + t] = v.z;
        s_h[(c4*4+3)*64 + t] = v.w;
    }
    __syncthreads();

    float h1t[64];
    #pragma unroll
    for (int ob = 0; ob < 8; ob++) {
        float acc[8];
        #pragma unroll
        for (int j = 0; j < 8; j++) acc[j] = 0.f;
        for (int c = 0; c < 64; c++) {
            float hv = s_h[c*64 + t];
            float4 w0 = *(const float4*)(s_wb + c*64 + ob*8);
            float4 w1 = *(const float4*)(s_wb + c*64 + ob*8 + 4);
            acc[0] = fmaf(hv, w0.x, acc[0]); acc[1] = fmaf(hv, w0.y, acc[1]);
            acc[2] = fmaf(hv, w0.z, acc[2]); acc[3] = fmaf(hv, w0.w, acc[3]);
            acc[4] = fmaf(hv, w1.x, acc[4]); acc[5] = fmaf(hv, w1.y, acc[5]);
            acc[6] = fmaf(hv, w1.z, acc[6]); acc[7] = fmaf(hv, w1.w, acc[7]);
        }
        #pragma unroll
        for (int j = 0; j < 8; j++) h1t[ob*8+j] = acc[j] + s_bb[ob*8+j];
    }

    float a[3] = {0.f, 0.f, 0.f};
    #pragma unroll
    for (int c = 0; c < 64; c++) {
        float hv = h1t[c];
        a[0] = fmaf(hv, s_wi[c],       a[0]);
        a[1] = fmaf(hv, s_wi[64 + c],  a[1]);
        a[2] = fmaf(hv, s_wi[128 + c], a[2]);
    }
    int b = pix / NPIX; int p = pix - b*NPIX;
    const float mn[3]  = {0.485f, 0.456f, 0.406f};
    const float sd[3]  = {0.229f, 0.224f, 0.225f};
    #pragma unroll
    for (int j = 0; j < 3; j++) {
        float pre = a[j] + biv[j];
        float s = 1.f/(1.f + expf(-pre));
        out[((size_t)b*3 + j)*NPIX + p] = (s - mn[j])/sd[j];
    }
}

extern "C" void kernel_launch(void* const* d_in, const int* in_sizes, int n_in,
                              void* d_out, int out_size) {
    (void)in_sizes; (void)n_in; (void)out_size;
    const float* pc       = (const float*)d_in[0];
    const float* w_in     = (const float*)d_in[1];
    const float* b_in     = (const float*)d_in[2];
    const float* w_graph  = (const float*)d_in[3];
    const float* gn_g     = (const float*)d_in[4];
    const float* gn_b     = (const float*)d_in[5];
    const float* w_proj   = (const float*)d_in[6];
    const float* b_proj   = (const float*)d_in[7];
    const float* bb_w1    = (const float*)d_in[8];
    const float* bb_g1    = (const float*)d_in[9];
    const float* bb_b1    = (const float*)d_in[10];
    const float* bb_w2    = (const float*)d_in[11];
    const float* bb_g2    = (const float*)d_in[12];
    const float* bb_b2    = (const float*)d_in[13];
    const float* w_blkout = (const float*)d_in[14];
    const float* b_blkout = (const float*)d_in[15];
    const float* w_img    = (const float*)d_in[16];
    const float* b_img    = (const float*)d_in[17];
    float* out = (float*)d_out;

    cudaFuncSetAttribute(k_conv_mma, cudaFuncAttributeMaxDynamicSharedMemorySize, CONV_SMEM_BYTES);

    k_zero<<<(BB*NPIX*CH/4 + 255)/256, 256>>>();
    k_params<<<BB, 256>>>(pc);
    k_f0<<<(BB*NN_ + 255)/256, 256>>>(pc, w_in, b_in);
    k_knn<<<dim3(NN_/32, BB), 256>>>(pc);
    k_graph<<<(BB*NN_*KNN*CH + 255)/256, 256>>>(w_graph);
    k_mean<<<BB*4, 512>>>();
    k_var<<<BB*4, 512>>>();
    k_proj<<<BB*NN_, 64>>>(gn_g, gn_b, w_proj, b_proj);
    k_scatter<<<BB*NN_, 64>>>(pc);
    k_wprep<<<(2*9*8*32*16 + 255)/256, 256>>>(bb_w1, bb_w2);
    k_conv_mma<<<dim3(14,14,BB), 256, CONV_SMEM_BYTES>>>(0, bb_g1, bb_b1);
    k_conv_mma<<<dim3(14,14,BB), 256, CONV_SMEM_BYTES>>>(1, bb_g2, bb_b2);
    k_final<<<(BB*NPIX)/64, 64>>>(w_blkout, b_blkout, w_img, b_img, out);
}